// round 4
// baseline (speedup 1.0000x reference)
#include <cuda_runtime.h>
#include <cuda_bf16.h>
#include <math_constants.h>
#include <cstdint>

#define B_  16
#define C_  256
#define IC_ 32
#define M_  16384
#define TM_ 128
#define TILES_ (M_/TM_)            // 128
#define RSQRT_IC 0.17677669529663687f

// ---------------- scratch (__device__ globals; no allocation allowed) -------
__device__ float d_g[(size_t)B_*IC_*M_];               // 33.5 MB  g_x (biased)
__device__ float d_partG[(size_t)B_*TILES_*IC_*IC_];   // per-tile t.t^T
__device__ float d_partS[(size_t)B_*TILES_*IC_];       // per-tile sum(t)
__device__ float d_weff[(size_t)B_*IC_*C_];            // w_w @ attn  [j][c]
// weights pre-split to bf16 hi/lo, packed in mma.m16n8k16 B-fragment order
__device__ __align__(16) unsigned short d_Bhi[64*256];
__device__ __align__(16) unsigned short d_Blo[64*256];

// ---------------- helpers ----------------------------------------------------
__device__ __forceinline__ uint32_t smem_u32(const void* p) {
    uint32_t a;
    asm("{ .reg .u64 t; cvta.to.shared.u64 t, %1; cvt.u32.u64 %0, t; }" : "=r"(a) : "l"(p));
    return a;
}
#define CP_ASYNC16(dst, src) \
    asm volatile("cp.async.ca.shared.global [%0], [%1], 16;" :: "r"(dst), "l"(src))
#define CP_COMMIT() asm volatile("cp.async.commit_group;" ::: "memory")
#define CP_WAIT(n)  asm volatile("cp.async.wait_group %0;" :: "n"(n) : "memory")

__device__ __forceinline__ void mma_bf16(float* d, const uint32_t* a,
                                         uint32_t b0, uint32_t b1) {
    asm volatile(
        "mma.sync.aligned.m16n8k16.row.col.f32.bf16.bf16.f32 "
        "{%0,%1,%2,%3}, {%4,%5,%6,%7}, {%8,%9}, {%0,%1,%2,%3};"
        : "+f"(d[0]), "+f"(d[1]), "+f"(d[2]), "+f"(d[3])
        : "r"(a[0]), "r"(a[1]), "r"(a[2]), "r"(a[3]), "r"(b0), "r"(b1));
}

__device__ __forceinline__ void split_pack(float f0, float f1,
                                           uint32_t& hi, uint32_t& lo) {
    uint32_t b0 = __float_as_uint(f0), b1 = __float_as_uint(f1);
    hi = __byte_perm(b0, b1, 0x7632);                 // {hi16(f0), hi16(f1)}
    float l0 = f0 - __uint_as_float(b0 & 0xFFFF0000u);
    float l1 = f1 - __uint_as_float(b1 & 0xFFFF0000u);
    __nv_bfloat162 p = __floats2bfloat162_rn(l0, l1);
    lo = *reinterpret_cast<uint32_t*>(&p);
}

// ============================================================================
// k0: split weights to bf16 hi/lo in B-fragment layout (n 0..31 theta, 32..63 g)
// ============================================================================
__global__ void k0_prep(const float* __restrict__ g_w, const float* __restrict__ theta_w)
{
    int idx = blockIdx.x * 256 + threadIdx.x;    // 0..16383
    int n = idx >> 8, k = idx & 255;
    float wv = (n < 32) ? theta_w[n * C_ + k] : g_w[(n - 32) * C_ + k];
    uint32_t bits = __float_as_uint(wv);
    unsigned short hi = (unsigned short)(bits >> 16);
    float hif = __uint_as_float(bits & 0xFFFF0000u);
    unsigned short lo = __bfloat16_as_ushort(__float2bfloat16(wv - hif));
    int ks = k >> 4, kr = k & 15;
    int r = kr >> 3, ct = (kr & 7) >> 1, e = kr & 1;
    int nb = n >> 3, lane = (n & 7) * 4 + ct;
    int us = ((((ks * 8 + nb) * 32 + lane) * 2 + r) << 1) | e;
    d_Bhi[us] = hi;
    d_Blo[us] = lo;
}

// ============================================================================
// k1: per (batch, 128-pixel tile): D[128 m][64 n] = X^T @ [theta;g]^T
//   cp.async double-buffered over 8 chunks of 32 channels.
// ============================================================================
__global__ __launch_bounds__(256, 3) void k1_proj(
    const float* __restrict__ x,
    const float* __restrict__ g_b, const float* __restrict__ theta_b)
{
    __shared__ __align__(16) float Xs[2][32 * 132];  // 2 x 16896 B
    float* Ts = &Xs[0][0];                           // [m][33] after main loop

    const int t = threadIdx.x;
    const int w = t >> 5, lane = t & 31;
    const int gr = lane >> 2, ct = lane & 3;
    const int tile = blockIdx.x, b = blockIdx.y;
    const int mbase = tile * TM_;
    const int m0 = 16 * w + gr;

    // staging indices (per thread: 4 x 16B per chunk)
    const int srow0 = t >> 5;            // rows t>>5, +8, +16, +24 via kk
    const int sm4 = (t & 31) * 4;
    const float* xbase = x + (size_t)b * C_ * M_ + mbase;

    float acc[8][4];
#pragma unroll
    for (int i = 0; i < 8; i++)
#pragma unroll
        for (int j = 0; j < 4; j++) acc[i][j] = 0.f;

    const uint2* Bhi2 = (const uint2*)d_Bhi;
    const uint2* Blo2 = (const uint2*)d_Blo;

    // ---- prologue: stage chunks 0,1
#pragma unroll
    for (int pc = 0; pc < 2; pc++) {
        uint32_t dst = smem_u32(&Xs[pc][0]);
#pragma unroll
        for (int kk = 0; kk < 4; kk++) {
            int row = srow0 + kk * 8;
            CP_ASYNC16(dst + (uint32_t)(row * 132 + sm4) * 4,
                       xbase + (size_t)(pc * 32 + row) * M_ + sm4);
        }
        CP_COMMIT();
    }

#pragma unroll
    for (int ck = 0; ck < 8; ck++) {
        if (ck < 7) { CP_WAIT(1); } else { CP_WAIT(0); }
        __syncthreads();

        const float* Xb = &Xs[ck & 1][0];
#pragma unroll
        for (int ks = 0; ks < 2; ks++) {
            const int kb = ks * 16 + 2 * ct;
            float f00 = Xb[(kb + 0) * 132 + m0],     f01 = Xb[(kb + 1) * 132 + m0];
            float f10 = Xb[(kb + 0) * 132 + m0 + 8], f11 = Xb[(kb + 1) * 132 + m0 + 8];
            float f20 = Xb[(kb + 8) * 132 + m0],     f21 = Xb[(kb + 9) * 132 + m0];
            float f30 = Xb[(kb + 8) * 132 + m0 + 8], f31 = Xb[(kb + 9) * 132 + m0 + 8];
            uint32_t ahi[4], alo[4];
            split_pack(f00, f01, ahi[0], alo[0]);
            split_pack(f10, f11, ahi[1], alo[1]);
            split_pack(f20, f21, ahi[2], alo[2]);
            split_pack(f30, f31, ahi[3], alo[3]);

            const int ksg = ck * 2 + ks;
#pragma unroll
            for (int nb = 0; nb < 8; nb++) {
                uint2 bh = __ldg(&Bhi2[(ksg * 8 + nb) * 32 + lane]);
                uint2 bl = __ldg(&Blo2[(ksg * 8 + nb) * 32 + lane]);
                mma_bf16(acc[nb], ahi, bh.x, bh.y);   // hh
                mma_bf16(acc[nb], ahi, bl.x, bl.y);   // hl
                mma_bf16(acc[nb], alo, bh.x, bh.y);   // lh
            }
        }
        __syncthreads();

        if (ck + 2 < 8) {
            uint32_t dst = smem_u32(&Xs[ck & 1][0]);
#pragma unroll
            for (int kk = 0; kk < 4; kk++) {
                int row = srow0 + kk * 8;
                CP_ASYNC16(dst + (uint32_t)(row * 132 + sm4) * 4,
                           xbase + (size_t)((ck + 2) * 32 + row) * M_ + sm4);
            }
            CP_COMMIT();
        }
    }

    // ---- epilogue: theta -> Ts (smem), g -> d_g (gmem, +bias)
#pragma unroll
    for (int nb = 0; nb < 4; nb++) {
        int n = nb * 8 + 2 * ct;
        float tb0 = __ldg(&theta_b[n]), tb1 = __ldg(&theta_b[n + 1]);
        Ts[m0 * 33 + n]           = acc[nb][0] + tb0;
        Ts[m0 * 33 + n + 1]       = acc[nb][1] + tb1;
        Ts[(m0 + 8) * 33 + n]     = acc[nb][2] + tb0;
        Ts[(m0 + 8) * 33 + n + 1] = acc[nb][3] + tb1;
    }
#pragma unroll
    for (int nb = 4; nb < 8; nb++) {
        int n = (nb - 4) * 8 + 2 * ct;
        float gb0 = __ldg(&g_b[n]), gb1 = __ldg(&g_b[n + 1]);
        float* p0 = d_g + ((size_t)b * IC_ + n) * M_ + mbase;
        float* p1 = d_g + ((size_t)b * IC_ + n + 1) * M_ + mbase;
        p0[m0]     = acc[nb][0] + gb0;
        p1[m0]     = acc[nb][1] + gb1;
        p0[m0 + 8] = acc[nb][2] + gb0;
        p1[m0 + 8] = acc[nb][3] + gb1;
    }
    __syncthreads();

    // ---- partial Gram: warp w -> rows 4w..4w+3, lane j -> column j
    {
        const int j = lane;
        float gac[4] = {0.f, 0.f, 0.f, 0.f};
        float sac = 0.f;
        for (int m = 0; m < TM_; m++) {
            float tj = Ts[m * 33 + j];
#pragma unroll
            for (int ii = 0; ii < 4; ii++)
                gac[ii] += Ts[m * 33 + w * 4 + ii] * tj;
            if (w == 0) sac += tj;
        }
        float* pG = d_partG + (size_t)(b * TILES_ + tile) * IC_ * IC_;
#pragma unroll
        for (int ii = 0; ii < 4; ii++)
            pG[(w * 4 + ii) * IC_ + j] = gac[ii];
        if (w == 0)
            d_partS[(size_t)(b * TILES_ + tile) * IC_ + j] = sac;
    }
}

// ============================================================================
// k2 (one block per batch): reduce partials, sigma, softmax, fold w_eff
// ============================================================================
__global__ __launch_bounds__(256) void k2_attn(const float* __restrict__ w_w)
{
    __shared__ float gram[IC_ * IC_];
    __shared__ float mu[IC_];
    __shared__ float attn[IC_ * IC_];
    const int t = threadIdx.x, b = blockIdx.x;

    for (int e = t; e < IC_ * IC_; e += 256) {
        float s = 0.f;
        const float* p = d_partG + (size_t)b * TILES_ * IC_ * IC_ + e;
        for (int tl = 0; tl < TILES_; tl++) s += p[(size_t)tl * IC_ * IC_];
        gram[e] = s;
    }
    if (t < IC_) {
        float s = 0.f;
        const float* p = d_partS + (size_t)b * TILES_ * IC_ + t;
        for (int tl = 0; tl < TILES_; tl++) s += p[tl * IC_];
        mu[t] = s * (1.0f / M_);
    }
    __syncthreads();

    if (t < IC_) {
        float row[IC_];
        float mx = -CUDART_INF_F;
#pragma unroll
        for (int jj = 0; jj < IC_; jj++) {
            float v = (gram[t * IC_ + jj] * (1.0f / M_) - mu[t] * mu[jj]) * RSQRT_IC;
            row[jj] = v; mx = fmaxf(mx, v);
        }
        float sum = 0.f;
#pragma unroll
        for (int jj = 0; jj < IC_; jj++) { row[jj] = __expf(row[jj] - mx); sum += row[jj]; }
        float inv = 1.0f / sum;
#pragma unroll
        for (int jj = 0; jj < IC_; jj++) attn[t * IC_ + jj] = row[jj] * inv;
    }
    __syncthreads();

    {   // thread t == channel c
        int c = t;
        float ww[IC_];
#pragma unroll
        for (int ii = 0; ii < IC_; ii++) ww[ii] = w_w[c * IC_ + ii];
#pragma unroll
        for (int jj = 0; jj < IC_; jj++) {
            float s = 0.f;
#pragma unroll
            for (int ii = 0; ii < IC_; ii++) s += ww[ii] * attn[ii * IC_ + jj];
            d_weff[((size_t)b * IC_ + jj) * C_ + c] = s;
        }
    }
}

// ============================================================================
// k3: out[b][c][m] = sum_j weff[j][c]*g[j][m] + w_b[c] + x[b][c][m]
//   512 threads, c-block 128, m-tile 128; 8c x 4m per thread; vectorized wT
// ============================================================================
__global__ __launch_bounds__(512) void k3_out(
    const float* __restrict__ x, const float* __restrict__ w_b,
    float* __restrict__ out)
{
    __shared__ __align__(16) float gs[IC_ * 128];   // [j][m]  16 KB
    __shared__ __align__(16) float wT[IC_ * 128];   // [j][c]  16 KB

    const int t = threadIdx.x;
    const int tile = blockIdx.x, cb = blockIdx.y, b = blockIdx.z;
    const int mbase = tile * TM_;
    const int cbase = cb * 128;

#pragma unroll
    for (int k = 0; k < 2; k++) {                   // gs: 1024 float4
        int f = t + k * 512;
        int i = f >> 5, m4 = (f & 31) * 4;
        *(float4*)(gs + i * 128 + m4) =
            *(const float4*)(d_g + ((size_t)b * IC_ + i) * M_ + mbase + m4);
    }
#pragma unroll
    for (int k = 0; k < 2; k++) {                   // wT: 1024 float4
        int f = t + k * 512;
        int i = f >> 5, c4 = (f & 31) * 4;
        *(float4*)(wT + i * 128 + c4) =
            *(const float4*)(d_weff + ((size_t)b * IC_ + i) * C_ + cbase + c4);
    }
    __syncthreads();

    const int c0 = (t >> 5) * 8, m0 = (t & 31) * 4;
    float acc[8][4];
#pragma unroll
    for (int i = 0; i < 8; i++)
#pragma unroll
        for (int j = 0; j < 4; j++) acc[i][j] = 0.f;

#pragma unroll
    for (int i = 0; i < IC_; i++) {
        float4 gv = *(const float4*)(gs + i * 128 + m0);          // conflict-free
        float4 w0 = *(const float4*)(wT + i * 128 + c0);          // broadcast
        float4 w1 = *(const float4*)(wT + i * 128 + c0 + 4);      // broadcast
        acc[0][0] += w0.x * gv.x; acc[0][1] += w0.x * gv.y; acc[0][2] += w0.x * gv.z; acc[0][3] += w0.x * gv.w;
        acc[1][0] += w0.y * gv.x; acc[1][1] += w0.y * gv.y; acc[1][2] += w0.y * gv.z; acc[1][3] += w0.y * gv.w;
        acc[2][0] += w0.z * gv.x; acc[2][1] += w0.z * gv.y; acc[2][2] += w0.z * gv.z; acc[2][3] += w0.z * gv.w;
        acc[3][0] += w0.w * gv.x; acc[3][1] += w0.w * gv.y; acc[3][2] += w0.w * gv.z; acc[3][3] += w0.w * gv.w;
        acc[4][0] += w1.x * gv.x; acc[4][1] += w1.x * gv.y; acc[4][2] += w1.x * gv.z; acc[4][3] += w1.x * gv.w;
        acc[5][0] += w1.y * gv.x; acc[5][1] += w1.y * gv.y; acc[5][2] += w1.y * gv.z; acc[5][3] += w1.y * gv.w;
        acc[6][0] += w1.z * gv.x; acc[6][1] += w1.z * gv.y; acc[6][2] += w1.z * gv.z; acc[6][3] += w1.z * gv.w;
        acc[7][0] += w1.w * gv.x; acc[7][1] += w1.w * gv.y; acc[7][2] += w1.w * gv.z; acc[7][3] += w1.w * gv.w;
    }

    const size_t base = ((size_t)b * C_ + cbase + c0) * M_ + mbase + m0;
#pragma unroll
    for (int ii = 0; ii < 8; ii++) {
        float wb = __ldg(&w_b[cbase + c0 + ii]);
        float4 xv = *(const float4*)(x + base + (size_t)ii * M_);
        float4 o = make_float4(acc[ii][0] + wb + xv.x, acc[ii][1] + wb + xv.y,
                               acc[ii][2] + wb + xv.z, acc[ii][3] + wb + xv.w);
        *(float4*)(out + base + (size_t)ii * M_) = o;
    }
}

// ============================================================================
extern "C" void kernel_launch(void* const* d_in, const int* in_sizes, int n_in,
                              void* d_out, int out_size)
{
    const float* x       = (const float*)d_in[0];
    const float* g_w     = (const float*)d_in[1];
    const float* g_b     = (const float*)d_in[2];
    const float* theta_w = (const float*)d_in[3];
    const float* theta_b = (const float*)d_in[4];
    const float* w_w     = (const float*)d_in[5];
    const float* w_b     = (const float*)d_in[6];
    float* out = (float*)d_out;

    k0_prep<<<64, 256>>>(g_w, theta_w);
    k1_proj<<<dim3(TILES_, B_), 256>>>(x, g_b, theta_b);
    k2_attn<<<B_, 256>>>(w_w);
    k3_out<<<dim3(TILES_, 2, B_), 512>>>(x, w_b, out);
}

// round 5
// speedup vs baseline: 1.2024x; 1.2024x over previous
#include <cuda_runtime.h>
#include <cuda_bf16.h>
#include <math_constants.h>
#include <cstdint>

#define B_  16
#define C_  256
#define IC_ 32
#define M_  16384
#define TM_ 128
#define TILES_ (M_/TM_)            // 128
#define RSQRT_IC 0.17677669529663687f

// ---------------- scratch (__device__ globals; no allocation allowed) -------
__device__ float d_g[(size_t)B_*IC_*M_];               // 33.5 MB  g_x (biased)
__device__ float d_partG[(size_t)B_*TILES_*IC_*IC_];   // per-tile t.t^T
__device__ float d_partS[(size_t)B_*TILES_*IC_];       // per-tile sum(t)
__device__ float d_weff[(size_t)B_*IC_*C_];            // w_w @ attn  [j][c]
// weights pre-split to bf16 hi/lo, packed in mma.m16n8k16 B-fragment order
__device__ __align__(16) unsigned short d_Bhi[64*256];
__device__ __align__(16) unsigned short d_Blo[64*256];

// ---------------- helpers ----------------------------------------------------
__device__ __forceinline__ uint32_t smem_u32(const void* p) {
    uint32_t a;
    asm("{ .reg .u64 t; cvta.to.shared.u64 t, %1; cvt.u32.u64 %0, t; }" : "=r"(a) : "l"(p));
    return a;
}
#define CP_ASYNC16(dst, src) \
    asm volatile("cp.async.ca.shared.global [%0], [%1], 16;" :: "r"(dst), "l"(src))
#define CP_COMMIT() asm volatile("cp.async.commit_group;" ::: "memory")
#define CP_WAIT(n)  asm volatile("cp.async.wait_group %0;" :: "n"(n) : "memory")

__device__ __forceinline__ void mma_bf16(float* d, const uint32_t* a,
                                         uint32_t b0, uint32_t b1) {
    asm volatile(
        "mma.sync.aligned.m16n8k16.row.col.f32.bf16.bf16.f32 "
        "{%0,%1,%2,%3}, {%4,%5,%6,%7}, {%8,%9}, {%0,%1,%2,%3};"
        : "+f"(d[0]), "+f"(d[1]), "+f"(d[2]), "+f"(d[3])
        : "r"(a[0]), "r"(a[1]), "r"(a[2]), "r"(a[3]), "r"(b0), "r"(b1));
}

__device__ __forceinline__ void split_pack(float f0, float f1,
                                           uint32_t& hi, uint32_t& lo) {
    uint32_t b0 = __float_as_uint(f0), b1 = __float_as_uint(f1);
    hi = __byte_perm(b0, b1, 0x7632);                 // {hi16(f0), hi16(f1)}
    float l0 = f0 - __uint_as_float(b0 & 0xFFFF0000u);
    float l1 = f1 - __uint_as_float(b1 & 0xFFFF0000u);
    __nv_bfloat162 p = __floats2bfloat162_rn(l0, l1);
    lo = *reinterpret_cast<uint32_t*>(&p);
}

// ============================================================================
// k0: split weights to bf16 hi/lo in B-fragment layout (n 0..31 theta, 32..63 g)
// ============================================================================
__global__ void k0_prep(const float* __restrict__ g_w, const float* __restrict__ theta_w)
{
    int idx = blockIdx.x * 256 + threadIdx.x;    // 0..16383
    int n = idx >> 8, k = idx & 255;
    float wv = (n < 32) ? theta_w[n * C_ + k] : g_w[(n - 32) * C_ + k];
    uint32_t bits = __float_as_uint(wv);
    unsigned short hi = (unsigned short)(bits >> 16);
    float hif = __uint_as_float(bits & 0xFFFF0000u);
    unsigned short lo = __bfloat16_as_ushort(__float2bfloat16(wv - hif));
    int ks = k >> 4, kr = k & 15;
    int r = kr >> 3, ct = (kr & 7) >> 1, e = kr & 1;
    int nb = n >> 3, lane = (n & 7) * 4 + ct;
    int us = ((((ks * 8 + nb) * 32 + lane) * 2 + r) << 1) | e;
    d_Bhi[us] = hi;
    d_Blo[us] = lo;
}

// ============================================================================
// k1: per (batch, 128-pixel tile): D[128 m][64 n] = X^T @ [theta;g]^T
//   5-stage cp.async pipeline over 16 chunks of 16 channels (prefetch dist 4).
// ============================================================================
__global__ __launch_bounds__(256, 3) void k1_proj(
    const float* __restrict__ x,
    const float* __restrict__ g_b, const float* __restrict__ theta_b)
{
    __shared__ __align__(16) float Xs[5][16 * 132];  // 5 x 8448 B = 42240 B
    float* Ts = &Xs[0][0];                            // [m][33] after main loop

    const int t = threadIdx.x;
    const int w = t >> 5, lane = t & 31;
    const int gr = lane >> 2, ct = lane & 3;
    const int tile = blockIdx.x, b = blockIdx.y;
    const int mbase = tile * TM_;
    const int m0 = 16 * w + gr;

    const int srow = t >> 5;             // staging rows srow, srow+8
    const int sm4 = (t & 31) * 4;
    const float* xbase = x + (size_t)b * C_ * M_ + mbase;

    float acc[8][4];
#pragma unroll
    for (int i = 0; i < 8; i++)
#pragma unroll
        for (int j = 0; j < 4; j++) acc[i][j] = 0.f;

    const uint2* Bhi2 = (const uint2*)d_Bhi;
    const uint2* Blo2 = (const uint2*)d_Blo;

    // ---- prologue: stage chunks 0..3
#pragma unroll
    for (int pc = 0; pc < 4; pc++) {
        uint32_t dst = smem_u32(&Xs[pc][0]);
#pragma unroll
        for (int kk = 0; kk < 2; kk++) {
            int row = srow + kk * 8;
            CP_ASYNC16(dst + (uint32_t)(row * 132 + sm4) * 4,
                       xbase + (size_t)(pc * 16 + row) * M_ + sm4);
        }
        CP_COMMIT();
    }

#pragma unroll
    for (int ck = 0; ck < 16; ck++) {
        if (ck <= 12)      { CP_WAIT(3); }
        else if (ck == 13) { CP_WAIT(2); }
        else if (ck == 14) { CP_WAIT(1); }
        else               { CP_WAIT(0); }
        __syncthreads();

        const float* Xb = &Xs[ck % 5][0];
        {
            const int kb = 2 * ct;
            float f00 = Xb[(kb + 0) * 132 + m0],     f01 = Xb[(kb + 1) * 132 + m0];
            float f10 = Xb[(kb + 0) * 132 + m0 + 8], f11 = Xb[(kb + 1) * 132 + m0 + 8];
            float f20 = Xb[(kb + 8) * 132 + m0],     f21 = Xb[(kb + 9) * 132 + m0];
            float f30 = Xb[(kb + 8) * 132 + m0 + 8], f31 = Xb[(kb + 9) * 132 + m0 + 8];
            uint32_t ahi[4], alo[4];
            split_pack(f00, f01, ahi[0], alo[0]);
            split_pack(f10, f11, ahi[1], alo[1]);
            split_pack(f20, f21, ahi[2], alo[2]);
            split_pack(f30, f31, ahi[3], alo[3]);

#pragma unroll
            for (int nb = 0; nb < 8; nb++) {
                uint2 bh = __ldg(&Bhi2[(ck * 8 + nb) * 32 + lane]);
                uint2 bl = __ldg(&Blo2[(ck * 8 + nb) * 32 + lane]);
                mma_bf16(acc[nb], ahi, bh.x, bh.y);   // hh
                mma_bf16(acc[nb], ahi, bl.x, bl.y);   // hl
                mma_bf16(acc[nb], alo, bh.x, bh.y);   // lh
            }
        }

        if (ck + 4 < 16) {
            // buffer (ck+4)%5 == (ck-1)%5: freed by this iteration's barrier
            uint32_t dst = smem_u32(&Xs[(ck + 4) % 5][0]);
#pragma unroll
            for (int kk = 0; kk < 2; kk++) {
                int row = srow + kk * 8;
                CP_ASYNC16(dst + (uint32_t)(row * 132 + sm4) * 4,
                           xbase + (size_t)((ck + 4) * 16 + row) * M_ + sm4);
            }
            CP_COMMIT();
        }
    }
    __syncthreads();   // all compute done; Xs reusable as Ts

    // ---- epilogue: theta -> Ts (smem), g -> d_g (gmem, +bias)
#pragma unroll
    for (int nb = 0; nb < 4; nb++) {
        int n = nb * 8 + 2 * ct;
        float tb0 = __ldg(&theta_b[n]), tb1 = __ldg(&theta_b[n + 1]);
        Ts[m0 * 33 + n]           = acc[nb][0] + tb0;
        Ts[m0 * 33 + n + 1]       = acc[nb][1] + tb1;
        Ts[(m0 + 8) * 33 + n]     = acc[nb][2] + tb0;
        Ts[(m0 + 8) * 33 + n + 1] = acc[nb][3] + tb1;
    }
#pragma unroll
    for (int nb = 4; nb < 8; nb++) {
        int n = (nb - 4) * 8 + 2 * ct;
        float gb0 = __ldg(&g_b[n]), gb1 = __ldg(&g_b[n + 1]);
        float* p0 = d_g + ((size_t)b * IC_ + n) * M_ + mbase;
        float* p1 = d_g + ((size_t)b * IC_ + n + 1) * M_ + mbase;
        p0[m0]     = acc[nb][0] + gb0;
        p1[m0]     = acc[nb][1] + gb1;
        p0[m0 + 8] = acc[nb][2] + gb0;
        p1[m0 + 8] = acc[nb][3] + gb1;
    }
    __syncthreads();

    // ---- partial Gram: warp w -> rows 4w..4w+3, lane j -> column j
    {
        const int j = lane;
        float gac[4] = {0.f, 0.f, 0.f, 0.f};
        float sac = 0.f;
        for (int m = 0; m < TM_; m++) {
            float tj = Ts[m * 33 + j];
#pragma unroll
            for (int ii = 0; ii < 4; ii++)
                gac[ii] += Ts[m * 33 + w * 4 + ii] * tj;
            if (w == 0) sac += tj;
        }
        float* pG = d_partG + (size_t)(b * TILES_ + tile) * IC_ * IC_;
#pragma unroll
        for (int ii = 0; ii < 4; ii++)
            pG[(w * 4 + ii) * IC_ + j] = gac[ii];
        if (w == 0)
            d_partS[(size_t)(b * TILES_ + tile) * IC_ + j] = sac;
    }
}

// ============================================================================
// k2 (one block per batch): reduce partials, sigma, softmax, fold w_eff
// ============================================================================
__global__ __launch_bounds__(256) void k2_attn(const float* __restrict__ w_w)
{
    __shared__ float gram[IC_ * IC_];
    __shared__ float mu[IC_];
    __shared__ float attn[IC_ * IC_];
    const int t = threadIdx.x, b = blockIdx.x;

    for (int e = t; e < IC_ * IC_; e += 256) {
        float s = 0.f;
        const float* p = d_partG + (size_t)b * TILES_ * IC_ * IC_ + e;
        for (int tl = 0; tl < TILES_; tl++) s += p[(size_t)tl * IC_ * IC_];
        gram[e] = s;
    }
    if (t < IC_) {
        float s = 0.f;
        const float* p = d_partS + (size_t)b * TILES_ * IC_ + t;
        for (int tl = 0; tl < TILES_; tl++) s += p[tl * IC_];
        mu[t] = s * (1.0f / M_);
    }
    __syncthreads();

    if (t < IC_) {
        float row[IC_];
        float mx = -CUDART_INF_F;
#pragma unroll
        for (int jj = 0; jj < IC_; jj++) {
            float v = (gram[t * IC_ + jj] * (1.0f / M_) - mu[t] * mu[jj]) * RSQRT_IC;
            row[jj] = v; mx = fmaxf(mx, v);
        }
        float sum = 0.f;
#pragma unroll
        for (int jj = 0; jj < IC_; jj++) { row[jj] = __expf(row[jj] - mx); sum += row[jj]; }
        float inv = 1.0f / sum;
#pragma unroll
        for (int jj = 0; jj < IC_; jj++) attn[t * IC_ + jj] = row[jj] * inv;
    }
    __syncthreads();

    {   // thread t == channel c
        int c = t;
        float ww[IC_];
#pragma unroll
        for (int ii = 0; ii < IC_; ii++) ww[ii] = w_w[c * IC_ + ii];
#pragma unroll
        for (int jj = 0; jj < IC_; jj++) {
            float s = 0.f;
#pragma unroll
            for (int ii = 0; ii < IC_; ii++) s += ww[ii] * attn[ii * IC_ + jj];
            d_weff[((size_t)b * IC_ + jj) * C_ + c] = s;
        }
    }
}

// ============================================================================
// k3: out[b][c][m] = sum_j weff[j][c]*g[j][m] + w_b[c] + x[b][c][m]
//   256 threads; block = 32-pixel tile x ALL 256 channels (d_g read once).
//   thread: 8c x 4m; float4 wT reads; 4 CTAs/SM.
// ============================================================================
__global__ __launch_bounds__(256, 4) void k3_out(
    const float* __restrict__ x, const float* __restrict__ w_b,
    float* __restrict__ out)
{
    __shared__ __align__(16) float gs[IC_ * 32];    // [j][m]   4 KB
    __shared__ __align__(16) float wT[IC_ * C_];    // [j][c]  32 KB

    const int t = threadIdx.x;
    const int tile = blockIdx.x, b = blockIdx.y;
    const int mbase = tile * 32;

    {   // gs: 256 float4 (one per thread)
        int j = t >> 3, m4 = (t & 7) * 4;
        *(float4*)(gs + j * 32 + m4) =
            *(const float4*)(d_g + ((size_t)b * IC_ + j) * M_ + mbase + m4);
    }
#pragma unroll
    for (int k = 0; k < 8; k++) {                   // wT: 2048 float4
        int f = t + k * 256;
        int j = f >> 6, c4 = (f & 63) * 4;
        *(float4*)(wT + j * C_ + c4) =
            *(const float4*)(d_weff + ((size_t)b * IC_ + j) * C_ + c4);
    }
    __syncthreads();

    const int m0 = (t & 7) * 4, c0 = (t >> 3) * 8;
    float acc[8][4];
#pragma unroll
    for (int i = 0; i < 8; i++)
#pragma unroll
        for (int j = 0; j < 4; j++) acc[i][j] = 0.f;

#pragma unroll
    for (int i = 0; i < IC_; i++) {
        float4 gv = *(const float4*)(gs + i * 32 + m0);           // broadcast groups
        float4 w0 = *(const float4*)(wT + i * C_ + c0);           // broadcast
        float4 w1 = *(const float4*)(wT + i * C_ + c0 + 4);       // broadcast
        acc[0][0] += w0.x * gv.x; acc[0][1] += w0.x * gv.y; acc[0][2] += w0.x * gv.z; acc[0][3] += w0.x * gv.w;
        acc[1][0] += w0.y * gv.x; acc[1][1] += w0.y * gv.y; acc[1][2] += w0.y * gv.z; acc[1][3] += w0.y * gv.w;
        acc[2][0] += w0.z * gv.x; acc[2][1] += w0.z * gv.y; acc[2][2] += w0.z * gv.z; acc[2][3] += w0.z * gv.w;
        acc[3][0] += w0.w * gv.x; acc[3][1] += w0.w * gv.y; acc[3][2] += w0.w * gv.z; acc[3][3] += w0.w * gv.w;
        acc[4][0] += w1.x * gv.x; acc[4][1] += w1.x * gv.y; acc[4][2] += w1.x * gv.z; acc[4][3] += w1.x * gv.w;
        acc[5][0] += w1.y * gv.x; acc[5][1] += w1.y * gv.y; acc[5][2] += w1.y * gv.z; acc[5][3] += w1.y * gv.w;
        acc[6][0] += w1.z * gv.x; acc[6][1] += w1.z * gv.y; acc[6][2] += w1.z * gv.z; acc[6][3] += w1.z * gv.w;
        acc[7][0] += w1.w * gv.x; acc[7][1] += w1.w * gv.y; acc[7][2] += w1.w * gv.z; acc[7][3] += w1.w * gv.w;
    }

    const size_t base = ((size_t)b * C_ + c0) * M_ + mbase + m0;
#pragma unroll
    for (int ii = 0; ii < 8; ii++) {
        float wb = __ldg(&w_b[c0 + ii]);
        float4 xv = *(const float4*)(x + base + (size_t)ii * M_);
        float4 o = make_float4(acc[ii][0] + wb + xv.x, acc[ii][1] + wb + xv.y,
                               acc[ii][2] + wb + xv.z, acc[ii][3] + wb + xv.w);
        *(float4*)(out + base + (size_t)ii * M_) = o;
    }
}

// ============================================================================
extern "C" void kernel_launch(void* const* d_in, const int* in_sizes, int n_in,
                              void* d_out, int out_size)
{
    const float* x       = (const float*)d_in[0];
    const float* g_w     = (const float*)d_in[1];
    const float* g_b     = (const float*)d_in[2];
    const float* theta_w = (const float*)d_in[3];
    const float* theta_b = (const float*)d_in[4];
    const float* w_w     = (const float*)d_in[5];
    const float* w_b     = (const float*)d_in[6];
    float* out = (float*)d_out;

    k0_prep<<<64, 256>>>(g_w, theta_w);
    k1_proj<<<dim3(TILES_, B_), 256>>>(x, g_b, theta_b);
    k2_attn<<<B_, 256>>>(w_w);
    k3_out<<<dim3(M_ / 32, B_), 256>>>(x, w_b, out);
}